// round 10
// baseline (speedup 1.0000x reference)
#include <cuda_runtime.h>
#include <math.h>

// Router: RMSNorm -> x @ W^T (16384x128x2816) -> softmax -> top-8 (on PROBS,
// lowest-index tie-break, replicating XLA TopK) -> renorm -> *pes -> dense.
//
// fp32 GEMM with Blackwell packed fma.rn.f32x2 + per-tile local accumulation
// (error ~3e-7 pre-factor, below reference noise).

#define DM        2816
#define NE        128
#define TK        8
#define BM        128
#define BK        16
#define NTHREADS  256
#define KIT       (DM / BK)   // 176
#define AST       132         // GEMM smem tile stride (padded)
#define SST       133         // score tile stride (odd -> conflict-free)
#define RMS_EPS   1e-6f
#define FULLMASK  0xffffffffu

typedef unsigned long long u64;

__device__ __forceinline__ u64 pk2(float lo, float hi) {
    u64 r; asm("mov.b64 %0, {%1, %2};" : "=l"(r) : "f"(lo), "f"(hi)); return r;
}
__device__ __forceinline__ u64 pkdup(float v) {
    u64 r; asm("mov.b64 %0, {%1, %1};" : "=l"(r) : "f"(v)); return r;
}
__device__ __forceinline__ float2 upk2(u64 v) {
    float2 r; asm("mov.b64 {%0, %1}, %2;" : "=f"(r.x), "=f"(r.y) : "l"(v)); return r;
}
__device__ __forceinline__ void ffma2(u64& d, u64 a, u64 b) {
    asm("fma.rn.f32x2 %0, %1, %2, %0;" : "+l"(d) : "l"(a), "l"(b));
}
__device__ __forceinline__ void fadd2(u64& d, u64 a) {
    asm("add.rn.f32x2 %0, %0, %1;" : "+l"(d) : "l"(a));
}

struct GemmSmem {
    float As[2][BK][AST];   // 16896 B
    float Bs[2][BK][AST];   // 16896 B (total 33792 B)
};
union RouterSmem {
    GemmSmem g;
    float S[64][SST];       // 34048 B (aliases GEMM buffers; used after)
};

__global__ void __launch_bounds__(NTHREADS)
router_kernel(const float* __restrict__ x,
              const float* __restrict__ w,
              const float* __restrict__ scale,
              const float* __restrict__ pes,
              float* __restrict__ out)
{
    __shared__ __align__(16) RouterSmem sm;
    __shared__ float frow[BM];
    __shared__ float pesh[NE];

    const int tid  = threadIdx.x;
    const int tx   = tid & 15;          // col group (8 experts)
    const int ty   = tid >> 4;          // row group (8 tokens)
    const int r0   = ty * 8;
    const int c0   = tx * 8;
    const int lrow = tid >> 2;          // 0..63 : load row
    const int kc4  = (tid & 3) * 4;     // 0,4,8,12 : load k-offset

    const size_t rowbase = (size_t)blockIdx.x * BM;
    const float* xa = x + (rowbase + lrow) * DM + kc4;
    const float* xb = x + (rowbase + lrow + 64) * DM + kc4;
    const float* wa = w + (size_t)lrow * DM + kc4;
    const float* wb = w + (size_t)(lrow + 64) * DM + kc4;
    const float* scp = scale + kc4;

    if (tid < NE) pesh[tid] = pes[tid];

    u64 acc[8][4];
    #pragma unroll
    for (int i = 0; i < 8; i++)
        #pragma unroll
        for (int j = 0; j < 4; j++) acc[i][j] = 0ull;

    float ss0 = 0.f, ss1 = 0.f;          // sum of squares (RMSNorm)
    float4 ra0, ra1, rb0, rb1, rsc;

    auto ldg_tile = [&](int kt) {
        const int off = kt * BK;
        ra0 = *(const float4*)(xa + off);
        ra1 = *(const float4*)(xb + off);
        rb0 = *(const float4*)(wa + off);
        rb1 = *(const float4*)(wb + off);
        rsc = *(const float4*)(scp + off);
    };

    auto sts_tile = [&](int b) {
        ss0 = fmaf(ra0.x, ra0.x, ss0); ss0 = fmaf(ra0.y, ra0.y, ss0);
        ss0 = fmaf(ra0.z, ra0.z, ss0); ss0 = fmaf(ra0.w, ra0.w, ss0);
        ss1 = fmaf(ra1.x, ra1.x, ss1); ss1 = fmaf(ra1.y, ra1.y, ss1);
        ss1 = fmaf(ra1.z, ra1.z, ss1); ss1 = fmaf(ra1.w, ra1.w, ss1);
        sm.g.As[b][kc4 + 0][lrow]      = ra0.x;
        sm.g.As[b][kc4 + 1][lrow]      = ra0.y;
        sm.g.As[b][kc4 + 2][lrow]      = ra0.z;
        sm.g.As[b][kc4 + 3][lrow]      = ra0.w;
        sm.g.As[b][kc4 + 0][lrow + 64] = ra1.x;
        sm.g.As[b][kc4 + 1][lrow + 64] = ra1.y;
        sm.g.As[b][kc4 + 2][lrow + 64] = ra1.z;
        sm.g.As[b][kc4 + 3][lrow + 64] = ra1.w;
        sm.g.Bs[b][kc4 + 0][lrow]      = rb0.x * rsc.x;
        sm.g.Bs[b][kc4 + 1][lrow]      = rb0.y * rsc.y;
        sm.g.Bs[b][kc4 + 2][lrow]      = rb0.z * rsc.z;
        sm.g.Bs[b][kc4 + 3][lrow]      = rb0.w * rsc.w;
        sm.g.Bs[b][kc4 + 0][lrow + 64] = rb1.x * rsc.x;
        sm.g.Bs[b][kc4 + 1][lrow + 64] = rb1.y * rsc.y;
        sm.g.Bs[b][kc4 + 2][lrow + 64] = rb1.z * rsc.z;
        sm.g.Bs[b][kc4 + 3][lrow + 64] = rb1.w * rsc.w;
    };

    // Per-tile local accumulation: tile partials stay small (rms ~0.08), so the
    // 176 folds into the main acc dominate error at ~3e-7 instead of 1.05e-6.
    auto compute = [&](int b) {
        u64 tacc[8][4];
        #pragma unroll
        for (int i = 0; i < 8; i++)
            #pragma unroll
            for (int j = 0; j < 4; j++) tacc[i][j] = 0ull;
        #pragma unroll
        for (int kk = 0; kk < BK; kk++) {
            float4 a0 = *(const float4*)&sm.g.As[b][kk][r0];
            float4 a1 = *(const float4*)&sm.g.As[b][kk][r0 + 4];
            float4 b0 = *(const float4*)&sm.g.Bs[b][kk][c0];
            float4 b1 = *(const float4*)&sm.g.Bs[b][kk][c0 + 4];
            u64 bp[4];
            bp[0] = pk2(b0.x, b0.y); bp[1] = pk2(b0.z, b0.w);
            bp[2] = pk2(b1.x, b1.y); bp[3] = pk2(b1.z, b1.w);
            float av[8] = {a0.x, a0.y, a0.z, a0.w, a1.x, a1.y, a1.z, a1.w};
            #pragma unroll
            for (int i = 0; i < 8; i++) {
                u64 ai = pkdup(av[i]);
                #pragma unroll
                for (int j = 0; j < 4; j++) ffma2(tacc[i][j], ai, bp[j]);
            }
        }
        #pragma unroll
        for (int i = 0; i < 8; i++)
            #pragma unroll
            for (int j = 0; j < 4; j++) fadd2(acc[i][j], tacc[i][j]);
    };

    // ---- mainloop: double-buffered, register-staged ----
    ldg_tile(0);
    sts_tile(0);
    __syncthreads();
    int buf = 0;
    for (int kt = 1; kt < KIT; kt++) {
        ldg_tile(kt);
        compute(buf);
        sts_tile(buf ^ 1);
        __syncthreads();
        buf ^= 1;
    }
    compute(buf);
    __syncthreads();   // GEMM buffers dead -> safe to alias with S

    // ---- RMSNorm factor per row ----
    ss0 += __shfl_xor_sync(FULLMASK, ss0, 1);
    ss0 += __shfl_xor_sync(FULLMASK, ss0, 2);
    ss1 += __shfl_xor_sync(FULLMASK, ss1, 1);
    ss1 += __shfl_xor_sync(FULLMASK, ss1, 2);
    const float kInvSqrtD = (float)(1.0 / sqrt((double)DM));
    if ((tid & 3) == 0) {
        frow[lrow]      = (1.0f / sqrtf(ss0 * (1.0f / DM) + RMS_EPS)) * kInvSqrtD;
        frow[lrow + 64] = (1.0f / sqrtf(ss1 * (1.0f / DM) + RMS_EPS)) * kInvSqrtD;
    }
    __syncthreads();

    const int wid  = tid >> 5;
    const int lane = tid & 31;

    // ---- epilogue: 2 phases of 64 tokens, warp-per-token ----
    #pragma unroll
    for (int ph = 0; ph < 2; ph++) {
        if ((ty >> 3) == ph) {
            const int rr = r0 - ph * 64;
            #pragma unroll
            for (int i = 0; i < 8; i++) {
                float fi = frow[r0 + i];
                #pragma unroll
                for (int j = 0; j < 4; j++) {
                    float2 v = upk2(acc[i][j]);
                    sm.S[rr + i][c0 + 2 * j]     = v.x * fi;
                    sm.S[rr + i][c0 + 2 * j + 1] = v.y * fi;
                }
            }
        }
        __syncthreads();

        for (int it = 0; it < 8; it++) {
            const int lrowS = it * 8 + wid;               // 0..63
            float sv[4];
            int   pi[4];
            #pragma unroll
            for (int q = 0; q < 4; q++) {
                pi[q] = lane + 32 * q;
                sv[q] = sm.S[lrowS][pi[q]];
            }
            // exact row max
            float m = fmaxf(fmaxf(sv[0], sv[1]), fmaxf(sv[2], sv[3]));
            #pragma unroll
            for (int off = 16; off >= 1; off >>= 1)
                m = fmaxf(m, __shfl_xor_sync(FULLMASK, m, off));
            // softmax numerators (libdevice expf, matching XLA's __nv_expf)
            float ev[4];
            #pragma unroll
            for (int q = 0; q < 4; q++) ev[q] = expf(sv[q] - m);
            // Z: XLA-style row reduce — strided thread partials, shfl-down tree
            float z = ((ev[0] + ev[1]) + ev[2]) + ev[3];
            #pragma unroll
            for (int off = 16; off >= 1; off >>= 1)
                z += __shfl_down_sync(FULLMASK, z, off);
            z = __shfl_sync(FULLMASK, z, 0);
            // probs: IEEE division (matches XLA div.rn.f32) — quantization here
            // is what creates ties that TopK breaks by LOWEST index.
            float pv[4];
            #pragma unroll
            for (int q = 0; q < 4; q++) pv[q] = __fdiv_rn(ev[q], z);

            // top-8 on probs, lexicographic (p desc, idx asc) argmax x8
            float wv[TK]; int wi[TK];
            #pragma unroll
            for (int r = 0; r < TK; r++) {
                float bv = pv[0]; int bidx = pi[0];
                #pragma unroll
                for (int q = 1; q < 4; q++)
                    if (pv[q] > bv || (pv[q] == bv && pi[q] < bidx)) { bv = pv[q]; bidx = pi[q]; }
                #pragma unroll
                for (int off = 16; off >= 1; off >>= 1) {
                    float ov = __shfl_xor_sync(FULLMASK, bv, off);
                    int   oi = __shfl_xor_sync(FULLMASK, bidx, off);
                    if (ov > bv || (ov == bv && oi < bidx)) { bv = ov; bidx = oi; }
                }
                wv[r] = bv; wi[r] = bidx;
                #pragma unroll
                for (int q = 0; q < 4; q++)
                    if (pi[q] == bidx) pv[q] = -1e30f;
            }

            // renorm over the 8 selected probs (descending order, like ref)
            float sumw = wv[0];
            #pragma unroll
            for (int r = 1; r < TK; r++) sumw += wv[r];

            // dense scatter straight to gmem (coalesced 128B segments)
            float* op = out + (rowbase + (size_t)ph * 64 + lrowS) * NE;
            #pragma unroll
            for (int q = 0; q < 4; q++) {
                const int col = pi[q];
                float val = 0.f;
                #pragma unroll
                for (int r = 0; r < TK; r++)
                    if (wi[r] == col) val = __fdiv_rn(wv[r], sumw) * pesh[col];
                op[col] = val;
            }
        }
        __syncthreads();
    }
}

extern "C" void kernel_launch(void* const* d_in, const int* in_sizes, int n_in,
                              void* d_out, int out_size) {
    (void)n_in; (void)out_size;
    const float* x     = (const float*)d_in[0];   // (4,4096,2816) f32
    const float* w     = (const float*)d_in[1];   // (128,2816)    f32
    const float* scale = (const float*)d_in[2];   // (2816,)       f32
    const float* pes   = (const float*)d_in[3];   // (128,)        f32
    float* out = (float*)d_out;                   // (4,4096,128)  f32

    const int tokens = in_sizes[0] / DM;          // 16384
    dim3 grid(tokens / BM);                       // 128 CTAs
    router_kernel<<<grid, NTHREADS>>>(x, w, scale, pes, out);
}

// round 11
// speedup vs baseline: 1.3875x; 1.3875x over previous
#include <cuda_runtime.h>
#include <math.h>

// Router: RMSNorm -> x @ W^T (16384x128x2816) -> softmax -> top-8 (on PROBS,
// lowest-index tie-break) -> renorm -> *per_expert_scale -> dense (16384,128).
//
// R10: 512-thread CTAs (16 warps), pre-folded+transposed W (scale baked in),
// token-packed f32x2 accumulators (A pairs read directly from smem, no dup MOVs).

#define DM        2816
#define NE        128
#define TK        8
#define BM        128
#define BK        16
#define NTHREADS  512
#define KIT       (DM / BK)   // 176
#define AST       132         // GEMM smem tile stride (padded, 16B-aligned rows)
#define SST       133         // score tile stride (odd -> conflict-free scans)
#define RMS_EPS   1e-6f
#define FULLMASK  0xffffffffu

typedef unsigned long long u64;

__device__ __forceinline__ u64 pkdup(float v) {
    u64 r; asm("mov.b64 %0, {%1, %1};" : "=l"(r) : "f"(v)); return r;
}
__device__ __forceinline__ float2 upk2(u64 v) {
    float2 r; asm("mov.b64 {%0, %1}, %2;" : "=f"(r.x), "=f"(r.y) : "l"(v)); return r;
}
__device__ __forceinline__ void ffma2(u64& d, u64 a, u64 b) {
    asm("fma.rn.f32x2 %0, %1, %2, %0;" : "+l"(d) : "l"(a), "l"(b));
}
__device__ __forceinline__ void fadd2(u64& d, u64 a) {
    asm("add.rn.f32x2 %0, %0, %1;" : "+l"(d) : "l"(a));
}

// W pre-folded with `scale` and transposed to [K][E] (coalesced tile loads,
// no smem transpose for B). 1.44 MB — stays L2-resident across all CTAs.
__device__ float g_wt[DM * NE];

__global__ void fold_kernel(const float* __restrict__ w,
                            const float* __restrict__ scale) {
    __shared__ float t[32][33];
    const int k0 = blockIdx.y * 32, e0 = blockIdx.x * 32;
    const int tx = threadIdx.x, ty = threadIdx.y;      // (32, 8)
    #pragma unroll
    for (int i = 0; i < 4; i++)                        // coalesced along k
        t[ty + 8 * i][tx] = w[(size_t)(e0 + ty + 8 * i) * DM + k0 + tx];
    __syncthreads();
    #pragma unroll
    for (int i = 0; i < 4; i++) {                      // coalesced along e
        const int k = k0 + ty + 8 * i;
        g_wt[(size_t)k * NE + e0 + tx] = t[tx][ty + 8 * i] * scale[k];
    }
}

struct GemmSmem {
    float As[2][BK][AST];   // 8448 B each buf
    float Bs[2][BK][AST];   // 8448 B each buf  (total 33792 B)
};
union RouterSmem {
    GemmSmem g;
    float S[64][SST];       // 34048 B (aliases GEMM buffers; used after)
};

__global__ void __launch_bounds__(NTHREADS, 1)
router_kernel(const float* __restrict__ x,
              const float* __restrict__ pes,
              float* __restrict__ out)
{
    __shared__ __align__(16) RouterSmem sm;
    __shared__ float frow[BM];
    __shared__ float pesh[NE];

    const int tid  = threadIdx.x;
    const int tx   = tid & 31;          // 32 col groups x 4 experts
    const int ty   = tid >> 5;          // 16 row groups x 8 tokens (== warp id)
    const int r0   = ty * 8;
    const int c0   = tx * 4;
    const int lrow = tid >> 2;          // 0..127 : A load row
    const int kc4  = (tid & 3) * 4;     // 0,4,8,12 : A load k-offset
    const int kb   = tid >> 5;          // 0..15 : B load k-row
    const int cb   = (tid & 31) * 4;    // B load expert-offset

    const size_t rowbase = (size_t)blockIdx.x * BM;
    const float* xa = x + (rowbase + lrow) * DM + kc4;
    const float* wt = g_wt + (size_t)kb * NE + cb;

    if (tid < NE) pesh[tid] = pes[tid];

    u64 acc[4][4];                       // [token-pair][expert]
    #pragma unroll
    for (int i = 0; i < 4; i++)
        #pragma unroll
        for (int j = 0; j < 4; j++) acc[i][j] = 0ull;

    float ss = 0.f;                      // sum of squares (RMSNorm), row lrow
    float4 ra, rb;

    auto ldg_tile = [&](int kt) {
        ra = *(const float4*)(xa + kt * BK);
        rb = *(const float4*)(wt + (size_t)kt * BK * NE);
    };

    auto sts_tile = [&](int b) {
        ss = fmaf(ra.x, ra.x, ss); ss = fmaf(ra.y, ra.y, ss);
        ss = fmaf(ra.z, ra.z, ss); ss = fmaf(ra.w, ra.w, ss);
        // A: transpose to [k][token]
        sm.g.As[b][kc4 + 0][lrow] = ra.x;
        sm.g.As[b][kc4 + 1][lrow] = ra.y;
        sm.g.As[b][kc4 + 2][lrow] = ra.z;
        sm.g.As[b][kc4 + 3][lrow] = ra.w;
        // B: straight-through (already [k][e], scale pre-folded)
        *(float4*)&sm.g.Bs[b][kb][cb] = rb;
    };

    // Tile-local accumulation keeps dot-product error ~3e-7 (below ref noise).
    auto compute = [&](int b) {
        u64 tacc[4][4];
        #pragma unroll
        for (int i = 0; i < 4; i++)
            #pragma unroll
            for (int j = 0; j < 4; j++) tacc[i][j] = 0ull;
        #pragma unroll
        for (int kk = 0; kk < BK; kk++) {
            // A token-pairs straight from smem (warp-broadcast addresses)
            ulonglong2 ap0 = *(const ulonglong2*)&sm.g.As[b][kk][r0];
            ulonglong2 ap1 = *(const ulonglong2*)&sm.g.As[b][kk][r0 + 4];
            float4 b4 = *(const float4*)&sm.g.Bs[b][kk][c0];
            u64 bd[4] = { pkdup(b4.x), pkdup(b4.y), pkdup(b4.z), pkdup(b4.w) };
            u64 ap[4] = { ap0.x, ap0.y, ap1.x, ap1.y };
            #pragma unroll
            for (int i = 0; i < 4; i++)
                #pragma unroll
                for (int j = 0; j < 4; j++) ffma2(tacc[i][j], ap[i], bd[j]);
        }
        #pragma unroll
        for (int i = 0; i < 4; i++)
            #pragma unroll
            for (int j = 0; j < 4; j++) fadd2(acc[i][j], tacc[i][j]);
    };

    // ---- mainloop: double-buffered, register-staged ----
    ldg_tile(0);
    sts_tile(0);
    __syncthreads();
    int buf = 0;
    for (int kt = 1; kt < KIT; kt++) {
        ldg_tile(kt);
        compute(buf);
        sts_tile(buf ^ 1);
        __syncthreads();
        buf ^= 1;
    }
    compute(buf);
    __syncthreads();   // GEMM buffers dead -> safe to alias with S

    // ---- RMSNorm factor per row (4 loader threads per row) ----
    ss += __shfl_xor_sync(FULLMASK, ss, 1);
    ss += __shfl_xor_sync(FULLMASK, ss, 2);
    const float kInvSqrtD = (float)(1.0 / sqrt((double)DM));
    if ((tid & 3) == 0)
        frow[lrow] = (1.0f / sqrtf(ss * (1.0f / DM) + RMS_EPS)) * kInvSqrtD;
    __syncthreads();

    const int wid  = ty;
    const int lane = tid & 31;

    // ---- epilogue: 2 phases of 64 tokens ----
    #pragma unroll
    for (int ph = 0; ph < 2; ph++) {
        if ((ty >> 3) == ph) {
            const int rr = r0 - ph * 64;
            #pragma unroll
            for (int i = 0; i < 4; i++) {
                const int t0 = 2 * i;
                float f0 = frow[r0 + t0], f1 = frow[r0 + t0 + 1];
                #pragma unroll
                for (int j = 0; j < 4; j++) {
                    float2 v = upk2(acc[i][j]);
                    sm.S[rr + t0][c0 + j]     = v.x * f0;
                    sm.S[rr + t0 + 1][c0 + j] = v.y * f1;
                }
            }
        }
        __syncthreads();

        // warp-per-token selection: 16 warps x 4 iterations = 64 rows
        for (int it = 0; it < 4; it++) {
            const int lrowS = it * 16 + wid;
            float sv[4];
            int   pi[4];
            #pragma unroll
            for (int q = 0; q < 4; q++) {
                pi[q] = lane + 32 * q;
                sv[q] = sm.S[lrowS][pi[q]];
            }
            // exact row max
            float m = fmaxf(fmaxf(sv[0], sv[1]), fmaxf(sv[2], sv[3]));
            #pragma unroll
            for (int off = 16; off >= 1; off >>= 1)
                m = fmaxf(m, __shfl_xor_sync(FULLMASK, m, off));
            // softmax numerators (libdevice expf, matching XLA)
            float ev[4];
            #pragma unroll
            for (int q = 0; q < 4; q++) ev[q] = expf(sv[q] - m);
            // Z: strided partials + shfl-down tree
            float z = ((ev[0] + ev[1]) + ev[2]) + ev[3];
            #pragma unroll
            for (int off = 16; off >= 1; off >>= 1)
                z += __shfl_down_sync(FULLMASK, z, off);
            z = __shfl_sync(FULLMASK, z, 0);
            // probs via IEEE division — quantization creates the ties that
            // TopK breaks by LOWEST index.
            float pv[4];
            #pragma unroll
            for (int q = 0; q < 4; q++) pv[q] = __fdiv_rn(ev[q], z);

            // top-8 on probs, lexicographic (p desc, idx asc) argmax x8
            float wv[TK]; int wi[TK];
            #pragma unroll
            for (int r = 0; r < TK; r++) {
                float bv = pv[0]; int bidx = pi[0];
                #pragma unroll
                for (int q = 1; q < 4; q++)
                    if (pv[q] > bv || (pv[q] == bv && pi[q] < bidx)) { bv = pv[q]; bidx = pi[q]; }
                #pragma unroll
                for (int off = 16; off >= 1; off >>= 1) {
                    float ov = __shfl_xor_sync(FULLMASK, bv, off);
                    int   oi = __shfl_xor_sync(FULLMASK, bidx, off);
                    if (ov > bv || (ov == bv && oi < bidx)) { bv = ov; bidx = oi; }
                }
                wv[r] = bv; wi[r] = bidx;
                #pragma unroll
                for (int q = 0; q < 4; q++)
                    if (pi[q] == bidx) pv[q] = -1e30f;
            }

            float sumw = wv[0];
            #pragma unroll
            for (int r = 1; r < TK; r++) sumw += wv[r];

            // dense scatter straight to gmem (coalesced 128B rows)
            float* op = out + (rowbase + (size_t)ph * 64 + lrowS) * NE;
            #pragma unroll
            for (int q = 0; q < 4; q++) {
                const int col = pi[q];
                float val = 0.f;
                #pragma unroll
                for (int r = 0; r < TK; r++)
                    if (wi[r] == col) val = __fdiv_rn(wv[r], sumw) * pesh[col];
                op[col] = val;
            }
        }
        __syncthreads();
    }
}

extern "C" void kernel_launch(void* const* d_in, const int* in_sizes, int n_in,
                              void* d_out, int out_size) {
    (void)n_in; (void)out_size;
    const float* x     = (const float*)d_in[0];   // (4,4096,2816) f32
    const float* w     = (const float*)d_in[1];   // (128,2816)    f32
    const float* scale = (const float*)d_in[2];   // (2816,)       f32
    const float* pes   = (const float*)d_in[3];   // (128,)        f32
    float* out = (float*)d_out;                   // (4,4096,128)  f32

    dim3 fgrid(NE / 32, DM / 32);
    fold_kernel<<<fgrid, dim3(32, 8)>>>(w, scale);

    const int tokens = in_sizes[0] / DM;          // 16384
    router_kernel<<<tokens / BM, NTHREADS>>>(x, pes, out);
}